// round 1
// baseline (speedup 1.0000x reference)
#include <cuda_runtime.h>
#include <math.h>

#define HOPSZ 512
#define MAX_NHAR 128
#define N_MAX_WIN 4410
#define TWO_PI_D 6.283185307179586476925286766559
#define INV_TWO_PI_D 0.15915494309189533576888376337251

__global__ __launch_bounds__(256) void czt_direct_kernel(
    const float* __restrict__ x,
    const float* __restrict__ f0g,
    float* __restrict__ out,
    int T, int nframes)
{
    __shared__ float xw[N_MAX_WIN];
    __shared__ float red_r[256];
    __shared__ float red_i[256];

    const int frame = blockIdx.x;
    const int tid = threadIdx.x;

    // per-frame scalar setup (redundant per thread; cheap)
    double f0 = (double)f0g[frame];
    if (f0 < 40.0) f0 = 40.0;
    const double sr = 44100.0;
    int nhar = (int)fmin(floor(sr / f0 * 0.5), (double)MAX_NHAR);
    int winsize = 2 * (int)rint(sr / f0 * 2.0);           // round-half-even, matches jnp.round
    if (winsize > N_MAX_WIN) winsize = N_MAX_WIN;         // safety (cannot trigger for f0>=40)
    const double theta = TWO_PI_D * f0 / sr;

    // ---- phase 1: windowed frame into smem (fp32) ----
    const int base = frame * HOPSZ - winsize / 2;
    const float invn = 1.0f / (float)winsize;
    for (int j = tid; j < winsize; j += blockDim.x) {
        int gi = base + j;
        float xv = (gi >= 0 && gi < T) ? x[gi] : 0.0f;
        float a = 6.28318530717958647692f * ((float)j * invn);
        float w = 0.42f - 0.5f * cosf(a) + 0.08f * cosf(2.0f * a);
        xw[j] = xv * w;
    }
    __syncthreads();

    // ---- phase 2: thread (k, half) computes half of harmonic k's DFT sum ----
    const int k = tid & (MAX_NHAR - 1);
    const int half = tid >> 7;
    const bool active = (k < nhar);

    float ar = 0.0f, ai = 0.0f;

    if (active) {
        const double thk = theta * (double)(k + 1);       // per-sample phase step (<= ~pi + theta)
        // step rotor s = exp(-i*thk), from wrapped fp64 phase
        double thw = thk - TWO_PI_D * rint(thk * INV_TWO_PI_D);
        float sr_c, sr_s;
        sincosf((float)thw, &sr_s, &sr_c);
        const float srot = sr_c;
        const float sirot = -sr_s;

        const int hw = winsize >> 1;
        const int jb = half ? hw : 0;
        const int je = half ? winsize : hw;

        const int SEG = 64;
        for (int j0 = jb; j0 < je; j0 += SEG) {
            // resync rotor: w = exp(-i*thk*j0), phase wrapped exactly in fp64
            double ph = thk * (double)j0;
            ph -= TWO_PI_D * rint(ph * INV_TWO_PI_D);
            float cw, sw;
            sincosf((float)ph, &sw, &cw);
            float wr = cw, wi = -sw;
            int jend = j0 + SEG; if (jend > je) jend = je;
            #pragma unroll 4
            for (int j = j0; j < jend; ++j) {
                float xv = xw[j];
                ar = fmaf(xv, wr, ar);
                ai = fmaf(xv, wi, ai);
                float nr = wr * srot - wi * sirot;
                float ni = wr * sirot + wi * srot;
                wr = nr; wi = ni;
            }
        }
    }

    red_r[tid] = ar;
    red_i[tid] = ai;
    __syncthreads();

    // ---- epilogue: combine halves, scale, write ampl + phase ----
    if (tid < MAX_NHAR) {
        float ampl = 0.0f, phs = 0.0f;
        if (tid < nhar) {
            float rr = red_r[tid] + red_r[tid + 128];
            float ri = red_i[tid] + red_i[tid + 128];
            float scale = (float)(2.381 / (double)(winsize / 2 + 1));
            float yr = rr * scale;
            float yi = ri * scale;
            ampl = sqrtf(yr * yr + yi * yi);
            phs = atan2f(yi, yr);
        }
        out[tid * nframes + frame] = ampl;
        out[MAX_NHAR * nframes + tid * nframes + frame] = phs;
    }
}

extern "C" void kernel_launch(void* const* d_in, const int* in_sizes, int n_in,
                              void* d_out, int out_size) {
    const float* x  = (const float*)d_in[0];
    const float* f0 = (const float*)d_in[1];
    float* out = (float*)d_out;
    int T = in_sizes[0];
    int nframes = in_sizes[1];
    czt_direct_kernel<<<nframes, 256>>>(x, f0, out, T, nframes);
}